// round 15
// baseline (speedup 1.0000x reference)
#include <cuda_runtime.h>
#include <cuda_bf16.h>
#include <cstdint>

#define B_    32
#define T_    24
#define N_    512
#define BT    768
#define DIN   64
#define HID   128
#define EMB   16
#define DOUT  2
#define NEG   0.01f

// Inter-kernel scratch
__device__ __nv_bfloat16 g_hi[(size_t)BT * N_ * HID];
__device__ __nv_bfloat16 g_lo[(size_t)BT * N_ * HID];
__device__ float g_P[(size_t)EMB * DIN * HID];
__device__ float g_pbe[(size_t)EMB * HID];
__device__ __nv_bfloat16 g_wt_hi[(size_t)BT * HID * HID];
__device__ __nv_bfloat16 g_wt_lo[(size_t)BT * HID * HID];
__device__ __nv_bfloat16 g_we_hi[(size_t)N_ * HID * DIN];
__device__ __nv_bfloat16 g_we_lo[(size_t)N_ * HID * DIN];

__device__ __forceinline__ float lrelu(float x) { return x >= 0.f ? x : NEG * x; }

__device__ __forceinline__ uint32_t smem_u32(const void* p) {
    uint32_t a;
    asm("{ .reg .u64 t; cvta.to.shared.u64 t, %1; cvt.u32.u64 %0, t; }" : "=r"(a) : "l"(p));
    return a;
}
__device__ __forceinline__ void ldsm_x4(uint32_t* r, uint32_t addr) {
    asm volatile("ldmatrix.sync.aligned.m8n8.x4.shared.b16 {%0,%1,%2,%3}, [%4];"
                 : "=r"(r[0]), "=r"(r[1]), "=r"(r[2]), "=r"(r[3]) : "r"(addr));
}
__device__ __forceinline__ void mma_bf16(float* d, const uint32_t* a, uint32_t b0, uint32_t b1) {
    asm volatile("mma.sync.aligned.m16n8k16.row.col.f32.bf16.bf16.f32 "
                 "{%0,%1,%2,%3}, {%4,%5,%6,%7}, {%8,%9}, {%0,%1,%2,%3};"
                 : "+f"(d[0]), "+f"(d[1]), "+f"(d[2]), "+f"(d[3])
                 : "r"(a[0]), "r"(a[1]), "r"(a[2]), "r"(a[3]), "r"(b0), "r"(b1));
}
__device__ __forceinline__ uint32_t pack_bf16_hi(float a, float b) {
    __nv_bfloat16 ha = __float2bfloat16(a), hb = __float2bfloat16(b);
    return (uint32_t)*(uint16_t*)&ha | ((uint32_t)*(uint16_t*)&hb << 16);
}
__device__ __forceinline__ void split_pack(float a, float b, uint32_t& hp, uint32_t& lp) {
    __nv_bfloat16 ha = __float2bfloat16(a), hb = __float2bfloat16(b);
    hp = (uint32_t)*(uint16_t*)&ha | ((uint32_t)*(uint16_t*)&hb << 16);
    lp = pack_bf16_hi(a - __bfloat162float(ha), b - __bfloat162float(hb));
}

// ---------------------------------------------------------------------------
// k_init: out = b3 broadcast (out is poisoned; temporal atomicAdds partials)
// ---------------------------------------------------------------------------
__global__ void k_init(float* __restrict__ out, const float* __restrict__ b3)
{
    int idx = blockIdx.x * 256 + threadIdx.x;   // grid 3072 x 256 = 786432
    out[idx] = __ldg(b3 + (idx & 1));
}

// ---------------------------------------------------------------------------
// k_pre
// ---------------------------------------------------------------------------
__global__ void __launch_bounds__(256)
k_pre(const float* __restrict__ W1, const float* __restrict__ b1,
      const float* __restrict__ pool_w, const float* __restrict__ pool_b)
{
    extern __shared__ float sp[];
    float* W1s = sp;
    float* Pl  = sp + 16 * HID;

    const int d  = blockIdx.x;
    const int r0 = blockIdx.y * 16;
    const int t  = threadIdx.x;
    const int rg = t >> 4, cg = t & 15;

    for (int e = t; e < 16 * HID; e += 256) W1s[e] = W1[r0 * HID + e];
    for (int e = t; e < HID * HID; e += 256) Pl[e] = pool_w[(size_t)d * HID * HID + e];
    __syncthreads();

    float acc[8];
#pragma unroll
    for (int j = 0; j < 8; j++) acc[j] = 0.f;

    const float* ar = W1s + rg * HID;
    const float* wc = Pl + cg * 8;
#pragma unroll 4
    for (int k = 0; k < HID; k++) {
        float a = ar[k];
        float4 w0 = *(const float4*)(wc + k * HID);
        float4 w1 = *(const float4*)(wc + k * HID + 4);
        acc[0] += a * w0.x; acc[1] += a * w0.y; acc[2] += a * w0.z; acc[3] += a * w0.w;
        acc[4] += a * w1.x; acc[5] += a * w1.y; acc[6] += a * w1.z; acc[7] += a * w1.w;
    }
#pragma unroll
    for (int j = 0; j < 8; j++)
        g_P[(size_t)d * DIN * HID + (r0 + rg) * HID + cg * 8 + j] = acc[j];

    if (blockIdx.y == 0 && t < HID) {
        float s = pool_b[d * HID + t];
#pragma unroll 8
        for (int k = 0; k < HID; k++) s += b1[k] * Pl[k * HID + t];
        g_pbe[d * HID + t] = s;
    }
}

// ---------------------------------------------------------------------------
// k_wtem
// ---------------------------------------------------------------------------
#define WT_PSLD 132
#define WT_SM   (16 * 8 * WT_PSLD * 4 + 256)

__global__ void __launch_bounds__(256)
k_wtem(const float* __restrict__ time_eb, const float* __restrict__ pool_w)
{
    extern __shared__ float sp[];
    float* Ps  = sp;
    float* tes = sp + 16 * 8 * WT_PSLD;

    const int btg0 = blockIdx.x * 64;
    const int o0   = blockIdx.y * 8;
    const int t    = threadIdx.x;

#pragma unroll
    for (int it = 0; it < 64; it++) {
        int idx = t + it * 256;
        int d = idx >> 10, rem = idx & 1023;
        int i = rem >> 3, orel = rem & 7;
        Ps[d * (8 * WT_PSLD) + orel * WT_PSLD + i] =
            pool_w[(size_t)d * HID * HID + i * HID + o0 + orel];
    }
    __syncthreads();

    const int orel = t >> 5;
    const int i0   = (t & 31) * 4;

#pragma unroll 1
    for (int gq = 0; gq < 16; gq++) {
        const int bt0 = btg0 + gq * 4;
        if (t < 64) tes[t] = time_eb[(bt0 + (t >> 4)) * EMB + (t & 15)];
        __syncthreads();

        float acc[4][4];
#pragma unroll
        for (int b = 0; b < 4; b++)
#pragma unroll
            for (int q = 0; q < 4; q++) acc[b][q] = 0.f;

#pragma unroll
        for (int d = 0; d < EMB; d++) {
            float4 p = *(const float4*)(Ps + d * (8 * WT_PSLD) + orel * WT_PSLD + i0);
#pragma unroll
            for (int b = 0; b < 4; b++) {
                float te = tes[b * EMB + d];
                acc[b][0] += te * p.x; acc[b][1] += te * p.y;
                acc[b][2] += te * p.z; acc[b][3] += te * p.w;
            }
        }
#pragma unroll
        for (int b = 0; b < 4; b++) {
            uint2 hp, lp;
            split_pack(acc[b][0], acc[b][1], hp.x, lp.x);
            split_pack(acc[b][2], acc[b][3], hp.y, lp.y);
            size_t off = (size_t)(bt0 + b) * HID * HID + (o0 + orel) * HID + i0;
            *(uint2*)(g_wt_hi + off) = hp;
            *(uint2*)(g_wt_lo + off) = lp;
        }
        __syncthreads();
    }
}

// ---------------------------------------------------------------------------
// k_weff
// ---------------------------------------------------------------------------
#define WE_PSLD 68
#define WE_SM   (16 * 8 * WE_PSLD * 4 + 256)

__global__ void __launch_bounds__(256)
k_weff(const float* __restrict__ node_eb)
{
    extern __shared__ float sp[];
    float* Ps  = sp;
    float* nes = sp + 16 * 8 * WE_PSLD;

    const int ng0 = blockIdx.x * 64;
    const int o0  = blockIdx.y * 8;
    const int t   = threadIdx.x;

#pragma unroll
    for (int it = 0; it < 32; it++) {
        int idx = t + it * 256;
        int d = idx >> 9, rem = idx & 511;
        int i = rem >> 3, orel = rem & 7;
        Ps[d * (8 * WE_PSLD) + orel * WE_PSLD + i] =
            g_P[(size_t)d * DIN * HID + i * HID + o0 + orel];
    }
    __syncthreads();

    const int orel = t >> 5;
    const int i0   = (t & 31) * 2;

#pragma unroll 1
    for (int gq = 0; gq < 16; gq++) {
        const int n0 = ng0 + gq * 4;
        if (t < 64) nes[t] = node_eb[(n0 + (t >> 4)) * EMB + (t & 15)];
        __syncthreads();

        float acc[4][2];
#pragma unroll
        for (int b = 0; b < 4; b++) { acc[b][0] = 0.f; acc[b][1] = 0.f; }

#pragma unroll
        for (int d = 0; d < EMB; d++) {
            float2 p = *(const float2*)(Ps + d * (8 * WE_PSLD) + orel * WE_PSLD + i0);
#pragma unroll
            for (int b = 0; b < 4; b++) {
                float ne = nes[b * EMB + d];
                acc[b][0] += ne * p.x; acc[b][1] += ne * p.y;
            }
        }
#pragma unroll
        for (int b = 0; b < 4; b++) {
            uint32_t hp, lp;
            split_pack(acc[b][0], acc[b][1], hp, lp);
            size_t off = (size_t)(n0 + b) * HID * DIN + (o0 + orel) * DIN + i0;
            *(uint32_t*)(g_we_hi + off) = hp;
            *(uint32_t*)(g_we_lo + off) = lp;
        }
        __syncthreads();
    }
}

// ---------------------------------------------------------------------------
// Kernel A (spatial): 3 CTA/SM (lb 256,3), phase-reordered fragments.
// smem: [bsp 512][BHI 18432][BLO 18432][AHI 9216][ALO 9216] = 55808
// ---------------------------------------------------------------------------
#define SLD     144
#define SP_BSP  0
#define SP_BHI  512
#define SP_BLO  18944
#define SP_AHI  37376
#define SP_ALO  46592
#define SP_TOT  55808

__global__ void __launch_bounds__(256, 3)
k_spatial(const float* __restrict__ eb, const float* __restrict__ node_eb)
{
    extern __shared__ char smch[];
    const uint32_t smb = smem_u32(smch);
    float* bsp = (float*)(smch + SP_BSP);

    const int n   = blockIdx.x;
    const int t   = threadIdx.x;
    const int wid = t >> 5;
    const int l   = t & 31;

#pragma unroll
    for (int i = 0; i < 4; i++) {
        int c = t + i * 256;
        int r = c >> 3, q = c & 7;
        size_t src = (size_t)n * HID * DIN + r * DIN + q * 8;
        *(uint4*)(smch + SP_BHI + r * SLD + q * 16) = *(const uint4*)(g_we_hi + src);
        *(uint4*)(smch + SP_BLO + r * SLD + q * 16) = *(const uint4*)(g_we_lo + src);
    }
    if (t < HID) {
        float s = 0.f;
#pragma unroll
        for (int d = 0; d < EMB; d++) s += node_eb[n * EMB + d] * g_pbe[d * HID + t];
        bsp[t] = s;
    }

    const int mw = wid & 1, nw = wid >> 1;
    const int m0w = mw * 32, n0w = nw * 32;
    const int g  = l >> 2, tq = l & 3;
    const uint32_t aoff = (uint32_t)(((l & 7) + ((l >> 3) & 1) * 8) * SLD + ((l >> 4) & 1) * 16);
    const uint32_t boff = (uint32_t)(((l & 7) + ((l >> 4) & 1) * 8) * SLD + ((l >> 3) & 1) * 16);
    const uint32_t AbHi = smb + SP_AHI + (uint32_t)m0w * SLD + aoff;
    const uint32_t AbLo = smb + SP_ALO + (uint32_t)m0w * SLD + aoff;
    const uint32_t BbHi = smb + SP_BHI + (uint32_t)n0w * SLD + boff;
    const uint32_t BbLo = smb + SP_BLO + (uint32_t)n0w * SLD + boff;

    __syncthreads();

    const int c_base = blockIdx.y * (BT / 2);
#pragma unroll 1
    for (int tt = 0; tt < BT / 2; tt += 64) {
        const int c0 = c_base + tt;

#pragma unroll
        for (int i = 0; i < 4; i++) {
            int chunk = t + i * 256;
            int r = chunk >> 4, q = chunk & 15;
            float4 v = *(const float4*)(eb + ((size_t)(c0 + r) * N_ + n) * DIN + q * 4);
            uint2 uh, ul;
            split_pack(v.x, v.y, uh.x, ul.x);
            split_pack(v.z, v.w, uh.y, ul.y);
            *(uint2*)(smch + SP_AHI + r * SLD + q * 8) = uh;
            *(uint2*)(smch + SP_ALO + r * SLD + q * 8) = ul;
        }
        __syncthreads();

        float acc[2][4][4];
#pragma unroll
        for (int mi = 0; mi < 2; mi++)
#pragma unroll
            for (int nj = 0; nj < 4; nj++)
#pragma unroll
                for (int q = 0; q < 4; q++) acc[mi][nj][q] = 0.f;

#pragma unroll
        for (int kc = 0; kc < 4; kc++) {
            // phase 1: hi x hi
            uint32_t ah0[4], ah1[4], bhA[4], bhB[4];
            ldsm_x4(ah0, AbHi + kc * 32);
            ldsm_x4(ah1, AbHi + 16 * SLD + kc * 32);
            ldsm_x4(bhA, BbHi + kc * 32);
            ldsm_x4(bhB, BbHi + 16 * SLD + kc * 32);
            mma_bf16(acc[0][0], ah0, bhA[0], bhA[1]);
            mma_bf16(acc[0][1], ah0, bhA[2], bhA[3]);
            mma_bf16(acc[0][2], ah0, bhB[0], bhB[1]);
            mma_bf16(acc[0][3], ah0, bhB[2], bhB[3]);
            mma_bf16(acc[1][0], ah1, bhA[0], bhA[1]);
            mma_bf16(acc[1][1], ah1, bhA[2], bhA[3]);
            mma_bf16(acc[1][2], ah1, bhB[0], bhB[1]);
            mma_bf16(acc[1][3], ah1, bhB[2], bhB[3]);
            // phase 2: lo x hi
            uint32_t al0[4], al1[4];
            ldsm_x4(al0, AbLo + kc * 32);
            ldsm_x4(al1, AbLo + 16 * SLD + kc * 32);
            mma_bf16(acc[0][0], al0, bhA[0], bhA[1]);
            mma_bf16(acc[0][1], al0, bhA[2], bhA[3]);
            mma_bf16(acc[0][2], al0, bhB[0], bhB[1]);
            mma_bf16(acc[0][3], al0, bhB[2], bhB[3]);
            mma_bf16(acc[1][0], al1, bhA[0], bhA[1]);
            mma_bf16(acc[1][1], al1, bhA[2], bhA[3]);
            mma_bf16(acc[1][2], al1, bhB[0], bhB[1]);
            mma_bf16(acc[1][3], al1, bhB[2], bhB[3]);
            // phase 3: hi x lo
            uint32_t blA[4], blB[4];
            ldsm_x4(blA, BbLo + kc * 32);
            ldsm_x4(blB, BbLo + 16 * SLD + kc * 32);
            mma_bf16(acc[0][0], ah0, blA[0], blA[1]);
            mma_bf16(acc[0][1], ah0, blA[2], blA[3]);
            mma_bf16(acc[0][2], ah0, blB[0], blB[1]);
            mma_bf16(acc[0][3], ah0, blB[2], blB[3]);
            mma_bf16(acc[1][0], ah1, blA[0], blA[1]);
            mma_bf16(acc[1][1], ah1, blA[2], blA[3]);
            mma_bf16(acc[1][2], ah1, blB[0], blB[1]);
            mma_bf16(acc[1][3], ah1, blB[2], blB[3]);
        }

#pragma unroll
        for (int mi = 0; mi < 2; mi++) {
#pragma unroll
            for (int rh = 0; rh < 2; rh++) {
                const int row = m0w + 16 * mi + 8 * rh + g;
                const size_t base = ((size_t)(c0 + row) * N_ + n) * HID;
#pragma unroll
                for (int nj = 0; nj < 4; nj++) {
                    const int col = n0w + 8 * nj + 2 * tq;
                    float h0 = lrelu(acc[mi][nj][rh * 2 + 0] + bsp[col]);
                    float h1 = lrelu(acc[mi][nj][rh * 2 + 1] + bsp[col + 1]);
                    uint32_t hp, lp;
                    split_pack(h0, h1, hp, lp);
                    *(uint32_t*)(g_hi + base + col) = hp;
                    *(uint32_t*)(g_lo + base + col) = lp;
                }
            }
        }
        __syncthreads();
    }
}

// ---------------------------------------------------------------------------
// Kernel B (temporal): o-split. grid (BT, 2); CTA owns 64 o-cols, 8 n-tiles
// of 64 rows. Partial h@W3 atomicAdd'ed into pre-initialized out.
// smem: [btm 256][W3h 512][BHI 17408][BLO 17408][AHI 17408][ALO 17408] = 70400
// -> 3 CTA/SM (lb 256,3)
// ---------------------------------------------------------------------------
#define TLD     272
#define T2_BTM  0
#define T2_W3   256
#define T2_BHI  768
#define T2_BLO  18176
#define T2_AHI  35584
#define T2_ALO  52992
#define T2_TOT  70400

__global__ void __launch_bounds__(256, 3)
k_temporal(const float* __restrict__ time_eb,
           const float* __restrict__ pool_b,
           const float* __restrict__ W3,
           float* __restrict__ out)
{
    extern __shared__ char smch[];
    const uint32_t smb = smem_u32(smch);
    float* btm = (float*)(smch + T2_BTM);   // 64 cols (this half)
    float* W3h = (float*)(smch + T2_W3);    // 64 x 2

    const int bt  = blockIdx.x;
    const int oh  = blockIdx.y;             // o-half
    const int t   = threadIdx.x;
    const int wid = t >> 5;
    const int l   = t & 31;

    // B tile: 64 o-rows (this half) x 128 i, hi/lo
#pragma unroll
    for (int i = 0; i < 4; i++) {
        int c = t + i * 256;                // 0..1023
        int r = c >> 4, q = c & 15;
        size_t src = (size_t)bt * HID * HID + (oh * 64 + r) * HID + q * 8;
        *(uint4*)(smch + T2_BHI + r * TLD + q * 16) = *(const uint4*)(g_wt_hi + src);
        *(uint4*)(smch + T2_BLO + r * TLD + q * 16) = *(const uint4*)(g_wt_lo + src);
    }
    if (t < 64) {
        int o = oh * 64 + t;
        float s = 0.f;
#pragma unroll
        for (int d = 0; d < EMB; d++) s += time_eb[bt * EMB + d] * pool_b[d * HID + o];
        btm[t] = s;
    }
    if (t < 128) W3h[t] = W3[(oh * 64 + (t >> 1)) * DOUT + (t & 1)];

    // warp grid: 2 M-warps x 4 N-warps; warp tile 32 rows x 16 cols
    const int mw = wid & 1, nw = wid >> 1;
    const int m0w = mw * 32;
    const int g  = l >> 2, tq = l & 3;
    const uint32_t aoff = (uint32_t)(((l & 7) + ((l >> 3) & 1) * 8) * TLD + ((l >> 4) & 1) * 16);
    const uint32_t boff = (uint32_t)(((l & 7) + ((l >> 4) & 1) * 8) * TLD + ((l >> 3) & 1) * 16);
    const uint32_t AbHi = smb + T2_AHI + (uint32_t)m0w * TLD + aoff;
    const uint32_t AbLo = smb + T2_ALO + (uint32_t)m0w * TLD + aoff;
    const uint32_t BbHi = smb + T2_BHI + (uint32_t)(nw * 16) * TLD + boff;
    const uint32_t BbLo = smb + T2_BLO + (uint32_t)(nw * 16) * TLD + boff;

    __syncthreads();

#pragma unroll 1
    for (int tile = 0; tile < 8; tile++) {
        const int r0 = tile * 64;

        // A tile: 64 n-rows x 128 i, hi/lo
#pragma unroll
        for (int i = 0; i < 4; i++) {
            int c = t + i * 256;
            int r = c >> 4, q = c & 15;
            size_t src = ((size_t)bt * N_ + r0 + r) * HID + q * 8;
            *(uint4*)(smch + T2_AHI + r * TLD + q * 16) = *(const uint4*)(g_hi + src);
            *(uint4*)(smch + T2_ALO + r * TLD + q * 16) = *(const uint4*)(g_lo + src);
        }
        __syncthreads();

        float acc[2][2][4];
#pragma unroll
        for (int mi = 0; mi < 2; mi++)
#pragma unroll
            for (int nj = 0; nj < 2; nj++)
#pragma unroll
                for (int q = 0; q < 4; q++) acc[mi][nj][q] = 0.f;

#pragma unroll 2
        for (int kc = 0; kc < 8; kc++) {
            uint32_t ah0[4], ah1[4], bh[4];
            ldsm_x4(ah0, AbHi + kc * 32);
            ldsm_x4(ah1, AbHi + 16 * TLD + kc * 32);
            ldsm_x4(bh, BbHi + kc * 32);
            mma_bf16(acc[0][0], ah0, bh[0], bh[1]);
            mma_bf16(acc[0][1], ah0, bh[2], bh[3]);
            mma_bf16(acc[1][0], ah1, bh[0], bh[1]);
            mma_bf16(acc[1][1], ah1, bh[2], bh[3]);
            uint32_t al0[4], al1[4];
            ldsm_x4(al0, AbLo + kc * 32);
            ldsm_x4(al1, AbLo + 16 * TLD + kc * 32);
            mma_bf16(acc[0][0], al0, bh[0], bh[1]);
            mma_bf16(acc[0][1], al0, bh[2], bh[3]);
            mma_bf16(acc[1][0], al1, bh[0], bh[1]);
            mma_bf16(acc[1][1], al1, bh[2], bh[3]);
            uint32_t bl[4];
            ldsm_x4(bl, BbLo + kc * 32);
            mma_bf16(acc[0][0], ah0, bl[0], bl[1]);
            mma_bf16(acc[0][1], ah0, bl[2], bl[3]);
            mma_bf16(acc[1][0], ah1, bl[0], bl[1]);
            mma_bf16(acc[1][1], ah1, bl[2], bl[3]);
        }

        // epilogue: h = leaky(D + btm); partial @W3 over this warp's 16 cols
#pragma unroll
        for (int mi = 0; mi < 2; mi++) {
#pragma unroll
            for (int rh = 0; rh < 2; rh++) {
                const int row = m0w + 16 * mi + 8 * rh + g;
                float p0 = 0.f, p1 = 0.f;
#pragma unroll
                for (int nj = 0; nj < 2; nj++) {
                    int cl = nw * 16 + nj * 8 + 2 * tq;   // local col 0..63
                    float h0 = lrelu(acc[mi][nj][rh * 2 + 0] + btm[cl]);
                    float h1 = lrelu(acc[mi][nj][rh * 2 + 1] + btm[cl + 1]);
                    p0 += h0 * W3h[cl * 2 + 0] + h1 * W3h[(cl + 1) * 2 + 0];
                    p1 += h0 * W3h[cl * 2 + 1] + h1 * W3h[(cl + 1) * 2 + 1];
                }
                p0 += __shfl_xor_sync(0xffffffffu, p0, 1);
                p1 += __shfl_xor_sync(0xffffffffu, p1, 1);
                p0 += __shfl_xor_sync(0xffffffffu, p0, 2);
                p1 += __shfl_xor_sync(0xffffffffu, p1, 2);
                if (tq == 0) {
                    size_t o = ((size_t)bt * N_ + r0 + row) * DOUT;
                    atomicAdd(out + o + 0, p0);
                    atomicAdd(out + o + 1, p1);
                }
            }
        }
        __syncthreads();   // A tile consumed before next load
    }
}

// ---------------------------------------------------------------------------
extern "C" void kernel_launch(void* const* d_in, const int* in_sizes, int n_in,
                              void* d_out, int out_size)
{
    const float* eb   = (const float*)d_in[0];
    const float* teb  = (const float*)d_in[1];
    const float* neb  = (const float*)d_in[2];
    const float* W1   = (const float*)d_in[3];
    const float* b1   = (const float*)d_in[4];
    const float* W3   = (const float*)d_in[5];
    const float* b3   = (const float*)d_in[6];
    const float* pws  = (const float*)d_in[7];
    const float* pbs  = (const float*)d_in[8];
    const float* pwt  = (const float*)d_in[9];
    const float* pbt  = (const float*)d_in[10];
    float* out = (float*)d_out;

    const int smp = (16 * HID + HID * HID) * sizeof(float);

    cudaFuncSetAttribute((const void*)k_pre,      cudaFuncAttributeMaxDynamicSharedMemorySize, smp);
    cudaFuncSetAttribute((const void*)k_wtem,     cudaFuncAttributeMaxDynamicSharedMemorySize, WT_SM);
    cudaFuncSetAttribute((const void*)k_weff,     cudaFuncAttributeMaxDynamicSharedMemorySize, WE_SM);
    cudaFuncSetAttribute((const void*)k_spatial,  cudaFuncAttributeMaxDynamicSharedMemorySize, SP_TOT);
    cudaFuncSetAttribute((const void*)k_temporal, cudaFuncAttributeMaxDynamicSharedMemorySize, T2_TOT);

    k_init<<<3072, 256>>>(out, b3);
    k_pre<<<dim3(EMB, 4), 256, smp>>>(W1, b1, pws, pbs);
    k_wtem<<<dim3(12, 16), 256, WT_SM>>>(teb, pwt);
    k_weff<<<dim3(8, 16), 256, WE_SM>>>(neb);
    k_spatial<<<dim3(N_, 2), 256, SP_TOT>>>(eb, neb);
    k_temporal<<<dim3(BT, 2), 256, T2_TOT>>>(teb, pbt, W3, out);
}

// round 16
// speedup vs baseline: 1.0644x; 1.0644x over previous
#include <cuda_runtime.h>
#include <cuda_bf16.h>
#include <cstdint>

#define B_    32
#define T_    24
#define N_    512
#define BT    768
#define DIN   64
#define HID   128
#define EMB   16
#define DOUT  2
#define NEG   0.01f

// Inter-kernel scratch
__device__ __nv_bfloat16 g_hi[(size_t)BT * N_ * HID];
__device__ __nv_bfloat16 g_lo[(size_t)BT * N_ * HID];
__device__ float g_P[(size_t)EMB * DIN * HID];
__device__ float g_pbe[(size_t)EMB * HID];
__device__ __nv_bfloat16 g_wt_hi[(size_t)BT * HID * HID];
__device__ __nv_bfloat16 g_wt_lo[(size_t)BT * HID * HID];
__device__ __nv_bfloat16 g_we_hi[(size_t)N_ * HID * DIN];
__device__ __nv_bfloat16 g_we_lo[(size_t)N_ * HID * DIN];

__device__ __forceinline__ float lrelu(float x) { return x >= 0.f ? x : NEG * x; }

__device__ __forceinline__ uint32_t smem_u32(const void* p) {
    uint32_t a;
    asm("{ .reg .u64 t; cvta.to.shared.u64 t, %1; cvt.u32.u64 %0, t; }" : "=r"(a) : "l"(p));
    return a;
}
__device__ __forceinline__ void ldsm_x4(uint32_t* r, uint32_t addr) {
    asm volatile("ldmatrix.sync.aligned.m8n8.x4.shared.b16 {%0,%1,%2,%3}, [%4];"
                 : "=r"(r[0]), "=r"(r[1]), "=r"(r[2]), "=r"(r[3]) : "r"(addr));
}
__device__ __forceinline__ void mma_bf16(float* d, const uint32_t* a, uint32_t b0, uint32_t b1) {
    asm volatile("mma.sync.aligned.m16n8k16.row.col.f32.bf16.bf16.f32 "
                 "{%0,%1,%2,%3}, {%4,%5,%6,%7}, {%8,%9}, {%0,%1,%2,%3};"
                 : "+f"(d[0]), "+f"(d[1]), "+f"(d[2]), "+f"(d[3])
                 : "r"(a[0]), "r"(a[1]), "r"(a[2]), "r"(a[3]), "r"(b0), "r"(b1));
}
__device__ __forceinline__ void cp16(uint32_t s, const void* g) {
    asm volatile("cp.async.cg.shared.global [%0], [%1], 16;" :: "r"(s), "l"(g));
}
#define CP_COMMIT() asm volatile("cp.async.commit_group;" ::: "memory")
#define CP_WAIT0()  asm volatile("cp.async.wait_group 0;" ::: "memory")
#define CP_WAIT1()  asm volatile("cp.async.wait_group 1;" ::: "memory")

__device__ __forceinline__ uint32_t pack_bf16_hi(float a, float b) {
    __nv_bfloat16 ha = __float2bfloat16(a), hb = __float2bfloat16(b);
    return (uint32_t)*(uint16_t*)&ha | ((uint32_t)*(uint16_t*)&hb << 16);
}
__device__ __forceinline__ void split_pack(float a, float b, uint32_t& hp, uint32_t& lp) {
    __nv_bfloat16 ha = __float2bfloat16(a), hb = __float2bfloat16(b);
    hp = (uint32_t)*(uint16_t*)&ha | ((uint32_t)*(uint16_t*)&hb << 16);
    lp = pack_bf16_hi(a - __bfloat162float(ha), b - __bfloat162float(hb));
}

#define MMA_FUSED_24(acc, ah0, ah1, al0, al1, bhA, bhB, blA, blB) do {     \
    mma_bf16(acc[0][0], ah0, bhA[0], bhA[1]);                              \
    mma_bf16(acc[0][1], ah0, bhA[2], bhA[3]);                              \
    mma_bf16(acc[0][2], ah0, bhB[0], bhB[1]);                              \
    mma_bf16(acc[0][3], ah0, bhB[2], bhB[3]);                              \
    mma_bf16(acc[1][0], ah1, bhA[0], bhA[1]);                              \
    mma_bf16(acc[1][1], ah1, bhA[2], bhA[3]);                              \
    mma_bf16(acc[1][2], ah1, bhB[0], bhB[1]);                              \
    mma_bf16(acc[1][3], ah1, bhB[2], bhB[3]);                              \
    mma_bf16(acc[0][0], al0, bhA[0], bhA[1]);                              \
    mma_bf16(acc[0][1], al0, bhA[2], bhA[3]);                              \
    mma_bf16(acc[0][2], al0, bhB[0], bhB[1]);                              \
    mma_bf16(acc[0][3], al0, bhB[2], bhB[3]);                              \
    mma_bf16(acc[1][0], al1, bhA[0], bhA[1]);                              \
    mma_bf16(acc[1][1], al1, bhA[2], bhA[3]);                              \
    mma_bf16(acc[1][2], al1, bhB[0], bhB[1]);                              \
    mma_bf16(acc[1][3], al1, bhB[2], bhB[3]);                              \
    mma_bf16(acc[0][0], ah0, blA[0], blA[1]);                              \
    mma_bf16(acc[0][1], ah0, blA[2], blA[3]);                              \
    mma_bf16(acc[0][2], ah0, blB[0], blB[1]);                              \
    mma_bf16(acc[0][3], ah0, blB[2], blB[3]);                              \
    mma_bf16(acc[1][0], ah1, blA[0], blA[1]);                              \
    mma_bf16(acc[1][1], ah1, blA[2], blA[3]);                              \
    mma_bf16(acc[1][2], ah1, blB[0], blB[1]);                              \
    mma_bf16(acc[1][3], ah1, blB[2], blB[3]);                              \
} while (0)

// ---------------------------------------------------------------------------
// k_pre
// ---------------------------------------------------------------------------
__global__ void __launch_bounds__(256)
k_pre(const float* __restrict__ W1, const float* __restrict__ b1,
      const float* __restrict__ pool_w, const float* __restrict__ pool_b)
{
    extern __shared__ float sp[];
    float* W1s = sp;
    float* Pl  = sp + 16 * HID;

    const int d  = blockIdx.x;
    const int r0 = blockIdx.y * 16;
    const int t  = threadIdx.x;
    const int rg = t >> 4, cg = t & 15;

    for (int e = t; e < 16 * HID; e += 256) W1s[e] = W1[r0 * HID + e];
    for (int e = t; e < HID * HID; e += 256) Pl[e] = pool_w[(size_t)d * HID * HID + e];
    __syncthreads();

    float acc[8];
#pragma unroll
    for (int j = 0; j < 8; j++) acc[j] = 0.f;

    const float* ar = W1s + rg * HID;
    const float* wc = Pl + cg * 8;
#pragma unroll 4
    for (int k = 0; k < HID; k++) {
        float a = ar[k];
        float4 w0 = *(const float4*)(wc + k * HID);
        float4 w1 = *(const float4*)(wc + k * HID + 4);
        acc[0] += a * w0.x; acc[1] += a * w0.y; acc[2] += a * w0.z; acc[3] += a * w0.w;
        acc[4] += a * w1.x; acc[5] += a * w1.y; acc[6] += a * w1.z; acc[7] += a * w1.w;
    }
#pragma unroll
    for (int j = 0; j < 8; j++)
        g_P[(size_t)d * DIN * HID + (r0 + rg) * HID + cg * 8 + j] = acc[j];

    if (blockIdx.y == 0 && t < HID) {
        float s = pool_b[d * HID + t];
#pragma unroll 8
        for (int k = 0; k < HID; k++) s += b1[k] * Pl[k * HID + t];
        g_pbe[d * HID + t] = s;
    }
}

// ---------------------------------------------------------------------------
// k_wtem: grid (48, 16); each block serves 16 bt (4 gq groups of 4)
// ---------------------------------------------------------------------------
#define WT_PSLD 132
#define WT_SM   (16 * 8 * WT_PSLD * 4 + 256)

__global__ void __launch_bounds__(256)
k_wtem(const float* __restrict__ time_eb, const float* __restrict__ pool_w)
{
    extern __shared__ float sp[];
    float* Ps  = sp;
    float* tes = sp + 16 * 8 * WT_PSLD;

    const int btg0 = blockIdx.x * 16;
    const int o0   = blockIdx.y * 8;
    const int t    = threadIdx.x;

#pragma unroll
    for (int it = 0; it < 64; it++) {
        int idx = t + it * 256;
        int d = idx >> 10, rem = idx & 1023;
        int i = rem >> 3, orel = rem & 7;
        Ps[d * (8 * WT_PSLD) + orel * WT_PSLD + i] =
            pool_w[(size_t)d * HID * HID + i * HID + o0 + orel];
    }
    __syncthreads();

    const int orel = t >> 5;
    const int i0   = (t & 31) * 4;

#pragma unroll 1
    for (int gq = 0; gq < 4; gq++) {
        const int bt0 = btg0 + gq * 4;
        if (t < 64) tes[t] = time_eb[(bt0 + (t >> 4)) * EMB + (t & 15)];
        __syncthreads();

        float acc[4][4];
#pragma unroll
        for (int b = 0; b < 4; b++)
#pragma unroll
            for (int q = 0; q < 4; q++) acc[b][q] = 0.f;

#pragma unroll
        for (int d = 0; d < EMB; d++) {
            float4 p = *(const float4*)(Ps + d * (8 * WT_PSLD) + orel * WT_PSLD + i0);
#pragma unroll
            for (int b = 0; b < 4; b++) {
                float te = tes[b * EMB + d];
                acc[b][0] += te * p.x; acc[b][1] += te * p.y;
                acc[b][2] += te * p.z; acc[b][3] += te * p.w;
            }
        }
#pragma unroll
        for (int b = 0; b < 4; b++) {
            uint2 hp, lp;
            split_pack(acc[b][0], acc[b][1], hp.x, lp.x);
            split_pack(acc[b][2], acc[b][3], hp.y, lp.y);
            size_t off = (size_t)(bt0 + b) * HID * HID + (o0 + orel) * HID + i0;
            *(uint2*)(g_wt_hi + off) = hp;
            *(uint2*)(g_wt_lo + off) = lp;
        }
        __syncthreads();
    }
}

// ---------------------------------------------------------------------------
// k_weff: grid (32, 16); each block serves 16 n (4 gq groups of 4)
// ---------------------------------------------------------------------------
#define WE_PSLD 68
#define WE_SM   (16 * 8 * WE_PSLD * 4 + 256)

__global__ void __launch_bounds__(256)
k_weff(const float* __restrict__ node_eb)
{
    extern __shared__ float sp[];
    float* Ps  = sp;
    float* nes = sp + 16 * 8 * WE_PSLD;

    const int ng0 = blockIdx.x * 16;
    const int o0  = blockIdx.y * 8;
    const int t   = threadIdx.x;

#pragma unroll
    for (int it = 0; it < 32; it++) {
        int idx = t + it * 256;
        int d = idx >> 9, rem = idx & 511;
        int i = rem >> 3, orel = rem & 7;
        Ps[d * (8 * WE_PSLD) + orel * WE_PSLD + i] =
            g_P[(size_t)d * DIN * HID + i * HID + o0 + orel];
    }
    __syncthreads();

    const int orel = t >> 5;
    const int i0   = (t & 31) * 2;

#pragma unroll 1
    for (int gq = 0; gq < 4; gq++) {
        const int n0 = ng0 + gq * 4;
        if (t < 64) nes[t] = node_eb[(n0 + (t >> 4)) * EMB + (t & 15)];
        __syncthreads();

        float acc[4][2];
#pragma unroll
        for (int b = 0; b < 4; b++) { acc[b][0] = 0.f; acc[b][1] = 0.f; }

#pragma unroll
        for (int d = 0; d < EMB; d++) {
            float2 p = *(const float2*)(Ps + d * (8 * WE_PSLD) + orel * WE_PSLD + i0);
#pragma unroll
            for (int b = 0; b < 4; b++) {
                float ne = nes[b * EMB + d];
                acc[b][0] += ne * p.x; acc[b][1] += ne * p.y;
            }
        }
#pragma unroll
        for (int b = 0; b < 4; b++) {
            uint32_t hp, lp;
            split_pack(acc[b][0], acc[b][1], hp, lp);
            size_t off = (size_t)(n0 + b) * HID * DIN + (o0 + orel) * DIN + i0;
            *(uint32_t*)(g_we_hi + off) = hp;
            *(uint32_t*)(g_we_lo + off) = lp;
        }
        __syncthreads();
    }
}

// ---------------------------------------------------------------------------
// Kernel A (spatial): cp.async 2-stage raw-x ring + convert + fused MMA.
// grid (N_, 3): 4 tile-iterations of 64 bt-rows each.
// smem: [bsp 512][BHI 18432][BLO 18432][AHI 9216][ALO 9216][XRAW 2x17408]
// = 90624 B -> 2 CTA/SM
// ---------------------------------------------------------------------------
#define SLD     144
#define SP_BSP  0
#define SP_BHI  512
#define SP_BLO  18944
#define SP_AHI  37376
#define SP_ALO  46592
#define SP_XRAW 55808
#define SP_TOT  90624
#define SP_NT   (BT / 3)      // 256 bt-rows per CTA
#define SP_ITER 4             // 256 / 64

__device__ __forceinline__ void sp_load_x(uint32_t smb, const float* eb, int n,
                                          int c0, int stage, int t)
{
    uint32_t base = smb + SP_XRAW + (uint32_t)stage * 17408;
#pragma unroll
    for (int i = 0; i < 4; i++) {
        int chunk = t + i * 256;
        int r = chunk >> 4, q = chunk & 15;
        cp16(base + r * 272 + q * 16,
             eb + ((size_t)(c0 + r) * N_ + n) * DIN + q * 4);
    }
}

__global__ void __launch_bounds__(256, 2)
k_spatial(const float* __restrict__ eb, const float* __restrict__ node_eb)
{
    extern __shared__ char smch[];
    const uint32_t smb = smem_u32(smch);
    float* bsp = (float*)(smch + SP_BSP);

    const int n   = blockIdx.x;
    const int t   = threadIdx.x;
    const int wid = t >> 5;
    const int l   = t & 31;
    const int c_base = blockIdx.y * SP_NT;

    sp_load_x(smb, eb, n, c_base, 0, t);      CP_COMMIT();   // g0
    sp_load_x(smb, eb, n, c_base + 64, 1, t); CP_COMMIT();   // g1

#pragma unroll
    for (int i = 0; i < 4; i++) {
        int c = t + i * 256;
        int r = c >> 3, q = c & 7;
        size_t src = (size_t)n * HID * DIN + r * DIN + q * 8;
        *(uint4*)(smch + SP_BHI + r * SLD + q * 16) = *(const uint4*)(g_we_hi + src);
        *(uint4*)(smch + SP_BLO + r * SLD + q * 16) = *(const uint4*)(g_we_lo + src);
    }
    if (t < HID) {
        float s = 0.f;
#pragma unroll
        for (int d = 0; d < EMB; d++) s += node_eb[n * EMB + d] * g_pbe[d * HID + t];
        bsp[t] = s;
    }

    const int mw = wid & 1, nw = wid >> 1;
    const int m0w = mw * 32, n0w = nw * 32;
    const int g  = l >> 2, tq = l & 3;
    const uint32_t aoff = (uint32_t)(((l & 7) + ((l >> 3) & 1) * 8) * SLD + ((l >> 4) & 1) * 16);
    const uint32_t boff = (uint32_t)(((l & 7) + ((l >> 4) & 1) * 8) * SLD + ((l >> 3) & 1) * 16);
    const uint32_t AbHi = smb + SP_AHI + (uint32_t)m0w * SLD + aoff;
    const uint32_t AbLo = smb + SP_ALO + (uint32_t)m0w * SLD + aoff;
    const uint32_t BbHi = smb + SP_BHI + (uint32_t)n0w * SLD + boff;
    const uint32_t BbLo = smb + SP_BLO + (uint32_t)n0w * SLD + boff;

    CP_WAIT1();            // g0 (x tile 0) complete
    __syncthreads();

#pragma unroll 1
    for (int it = 0; it < SP_ITER; it++) {
        const int c0 = c_base + it * 64;

        const uint32_t xb = (uint32_t)(it & 1) * 17408;
#pragma unroll
        for (int i = 0; i < 4; i++) {
            int chunk = t + i * 256;
            int r = chunk >> 4, q = chunk & 15;
            float4 v = *(const float4*)(smch + SP_XRAW + xb + r * 272 + q * 16);
            uint2 uh, ul;
            split_pack(v.x, v.y, uh.x, ul.x);
            split_pack(v.z, v.w, uh.y, ul.y);
            *(uint2*)(smch + SP_AHI + r * SLD + q * 8) = uh;
            *(uint2*)(smch + SP_ALO + r * SLD + q * 8) = ul;
        }
        __syncthreads();

        if (it + 2 < SP_ITER) { sp_load_x(smb, eb, n, c_base + (it + 2) * 64, it & 1, t); CP_COMMIT(); }

        float acc[2][4][4];
#pragma unroll
        for (int mi = 0; mi < 2; mi++)
#pragma unroll
            for (int nj = 0; nj < 4; nj++)
#pragma unroll
                for (int q = 0; q < 4; q++) acc[mi][nj][q] = 0.f;

#pragma unroll
        for (int kc = 0; kc < 4; kc++) {
            uint32_t ah0[4], ah1[4], al0[4], al1[4], bhA[4], bhB[4], blA[4], blB[4];
            ldsm_x4(ah0, AbHi + kc * 32);
            ldsm_x4(ah1, AbHi + 16 * SLD + kc * 32);
            ldsm_x4(al0, AbLo + kc * 32);
            ldsm_x4(al1, AbLo + 16 * SLD + kc * 32);
            ldsm_x4(bhA, BbHi + kc * 32);
            ldsm_x4(bhB, BbHi + 16 * SLD + kc * 32);
            ldsm_x4(blA, BbLo + kc * 32);
            ldsm_x4(blB, BbLo + 16 * SLD + kc * 32);
            MMA_FUSED_24(acc, ah0, ah1, al0, al1, bhA, bhB, blA, blB);
        }

#pragma unroll
        for (int mi = 0; mi < 2; mi++) {
#pragma unroll
            for (int rh = 0; rh < 2; rh++) {
                const int row = m0w + 16 * mi + 8 * rh + g;
                const size_t base = ((size_t)(c0 + row) * N_ + n) * HID;
#pragma unroll
                for (int nj = 0; nj < 4; nj++) {
                    const int col = n0w + 8 * nj + 2 * tq;
                    float h0 = lrelu(acc[mi][nj][rh * 2 + 0] + bsp[col]);
                    float h1 = lrelu(acc[mi][nj][rh * 2 + 1] + bsp[col + 1]);
                    uint32_t hp, lp;
                    split_pack(h0, h1, hp, lp);
                    *(uint32_t*)(g_hi + base + col) = hp;
                    *(uint32_t*)(g_lo + base + col) = lp;
                }
            }
        }

        if (it + 2 < SP_ITER) CP_WAIT1(); else CP_WAIT0();
        __syncthreads();
    }
}

// ---------------------------------------------------------------------------
// Kernel B (temporal): 512 threads, one CTA per bt, M-tiles of 128 rows,
// cp.async 2-stage A ring. smem:
//   [btm 512][W3s 1024][pout 1024][BHI 34816][BLO 34816][A 2x69632] = 211456
// ---------------------------------------------------------------------------
#define TLD    272
#define T_BTM  0
#define T_W3   512
#define T_POUT 1536
#define T_BHI  2560
#define T_BLO  37376
#define T_AST  72192
#define T_TOT  211456

__device__ __forceinline__ void tm_load_a(uint32_t smb, int bt, int r0, int stage, int t)
{
    uint32_t base = smb + T_AST + (uint32_t)stage * 69632;
#pragma unroll
    for (int i = 0; i < 4; i++) {
        int idx = t + i * 512;
        int r = idx >> 4, q = idx & 15;
        size_t src = ((size_t)bt * N_ + r0 + r) * HID + q * 8;
        cp16(base + r * TLD + q * 16, g_hi + src);
        cp16(base + 34816 + r * TLD + q * 16, g_lo + src);
    }
}

__global__ void __launch_bounds__(512, 1)
k_temporal(const float* __restrict__ time_eb,
           const float* __restrict__ pool_b,
           const float* __restrict__ W3,
           const float* __restrict__ b3,
           float* __restrict__ out)
{
    extern __shared__ char smch[];
    const uint32_t smb = smem_u32(smch);
    float* btm  = (float*)(smch + T_BTM);
    float* W3s  = (float*)(smch + T_W3);
    float* pout = (float*)(smch + T_POUT);

    const int bt  = blockIdx.x;
    const int t   = threadIdx.x;
    const int wid = t >> 5;
    const int l   = t & 31;

#pragma unroll
    for (int i = 0; i < 4; i++) {
        int idx = t + i * 512;
        int r = idx >> 4, q = idx & 15;
        size_t src = (size_t)bt * HID * HID + r * HID + q * 8;
        cp16(smb + T_BHI + r * TLD + q * 16, g_wt_hi + src);
        cp16(smb + T_BLO + r * TLD + q * 16, g_wt_lo + src);
    }
    tm_load_a(smb, bt, 0, 0, t);
    CP_COMMIT();                         // g0
    tm_load_a(smb, bt, 128, 1, t);
    CP_COMMIT();                         // g1

    if (t < HID) {
        float s = 0.f;
#pragma unroll
        for (int d = 0; d < EMB; d++) s += time_eb[bt * EMB + d] * pool_b[d * HID + t];
        btm[t] = s;
    }
    if (t < HID * DOUT) W3s[t] = W3[t];
    const float b30 = __ldg(b3), b31 = __ldg(b3 + 1);
    if (t < 256) pout[t] = (t & 1) ? b31 : b30;

    const int mw = wid & 3, nw = wid >> 2;
    const int m0w = mw * 32, n0w = nw * 32;
    const int g  = l >> 2, tq = l & 3;
    const uint32_t aoff = (uint32_t)(((l & 7) + ((l >> 3) & 1) * 8) * TLD + ((l >> 4) & 1) * 16);
    const uint32_t boff = (uint32_t)(((l & 7) + ((l >> 4) & 1) * 8) * TLD + ((l >> 3) & 1) * 16);
    const uint32_t BbHi = smb + T_BHI + (uint32_t)n0w * TLD + boff;
    const uint32_t BbLo = BbHi + 34816;

    CP_WAIT1();            // g0 complete (B + A0)
    __syncthreads();

#pragma unroll 1
    for (int tile = 0; tile < 4; tile++) {
        const int r0 = tile * 128;
        const uint32_t AbHi = smb + T_AST + (uint32_t)(tile & 1) * 69632
                            + (uint32_t)m0w * TLD + aoff;
        const uint32_t AbLo = AbHi + 34816;

        float acc[2][4][4];
#pragma unroll
        for (int mi = 0; mi < 2; mi++)
#pragma unroll
            for (int nj = 0; nj < 4; nj++)
#pragma unroll
                for (int q = 0; q < 4; q++) acc[mi][nj][q] = 0.f;

#pragma unroll 2
        for (int kc = 0; kc < 8; kc++) {
            uint32_t ah0[4], ah1[4], al0[4], al1[4], bhA[4], bhB[4], blA[4], blB[4];
            ldsm_x4(ah0, AbHi + kc * 32);
            ldsm_x4(ah1, AbHi + 16 * TLD + kc * 32);
            ldsm_x4(al0, AbLo + kc * 32);
            ldsm_x4(al1, AbLo + 16 * TLD + kc * 32);
            ldsm_x4(bhA, BbHi + kc * 32);
            ldsm_x4(bhB, BbHi + 16 * TLD + kc * 32);
            ldsm_x4(blA, BbLo + kc * 32);
            ldsm_x4(blB, BbLo + 16 * TLD + kc * 32);
            MMA_FUSED_24(acc, ah0, ah1, al0, al1, bhA, bhB, blA, blB);
        }

#pragma unroll
        for (int mi = 0; mi < 2; mi++) {
#pragma unroll
            for (int rh = 0; rh < 2; rh++) {
                int rowl = m0w + 16 * mi + 8 * rh + g;
                float p0 = 0.f, p1 = 0.f;
#pragma unroll
                for (int nj = 0; nj < 4; nj++) {
                    int col = n0w + 8 * nj + 2 * tq;
                    float h0 = lrelu(acc[mi][nj][rh * 2 + 0] + btm[col]);
                    float h1 = lrelu(acc[mi][nj][rh * 2 + 1] + btm[col + 1]);
                    p0 += h0 * W3s[col * 2 + 0] + h1 * W3s[(col + 1) * 2 + 0];
                    p1 += h0 * W3s[col * 2 + 1] + h1 * W3s[(col + 1) * 2 + 1];
                }
                p0 += __shfl_xor_sync(0xffffffffu, p0, 1);
                p1 += __shfl_xor_sync(0xffffffffu, p1, 1);
                p0 += __shfl_xor_sync(0xffffffffu, p0, 2);
                p1 += __shfl_xor_sync(0xffffffffu, p1, 2);
                if (tq == 0) {
                    atomicAdd(&pout[rowl * 2 + 0], p0);
                    atomicAdd(&pout[rowl * 2 + 1], p1);
                }
            }
        }
        __syncthreads();   // pout complete; stage[tile&1] fully consumed

        if (t < 256) out[((size_t)bt * N_ + r0) * DOUT + t] = pout[t];

        if (tile < 3) {
            if (t < 256) pout[t] = (t & 1) ? b31 : b30;
            if (tile < 2) {
                tm_load_a(smb, bt, (tile + 2) * 128, tile & 1, t);
                CP_COMMIT();
                CP_WAIT1();
            } else {
                CP_WAIT0();
            }
            __syncthreads();
        }
    }
}

// ---------------------------------------------------------------------------
extern "C" void kernel_launch(void* const* d_in, const int* in_sizes, int n_in,
                              void* d_out, int out_size)
{
    const float* eb   = (const float*)d_in[0];
    const float* teb  = (const float*)d_in[1];
    const float* neb  = (const float*)d_in[2];
    const float* W1   = (const float*)d_in[3];
    const float* b1   = (const float*)d_in[4];
    const float* W3   = (const float*)d_in[5];
    const float* b3   = (const float*)d_in[6];
    const float* pws  = (const float*)d_in[7];
    const float* pbs  = (const float*)d_in[8];
    const float* pwt  = (const float*)d_in[9];
    const float* pbt  = (const float*)d_in[10];
    float* out = (float*)d_out;

    const int smp = (16 * HID + HID * HID) * sizeof(float);

    cudaFuncSetAttribute((const void*)k_pre,      cudaFuncAttributeMaxDynamicSharedMemorySize, smp);
    cudaFuncSetAttribute((const void*)k_wtem,     cudaFuncAttributeMaxDynamicSharedMemorySize, WT_SM);
    cudaFuncSetAttribute((const void*)k_weff,     cudaFuncAttributeMaxDynamicSharedMemorySize, WE_SM);
    cudaFuncSetAttribute((const void*)k_spatial,  cudaFuncAttributeMaxDynamicSharedMemorySize, SP_TOT);
    cudaFuncSetAttribute((const void*)k_temporal, cudaFuncAttributeMaxDynamicSharedMemorySize, T_TOT);

    k_pre<<<dim3(EMB, 4), 256, smp>>>(W1, b1, pws, pbs);
    k_wtem<<<dim3(48, 16), 256, WT_SM>>>(teb, pwt);
    k_weff<<<dim3(32, 16), 256, WE_SM>>>(neb);
    k_spatial<<<dim3(N_, 3), 256, SP_TOT>>>(eb, neb);
    k_temporal<<<BT, 512, T_TOT>>>(teb, pbt, W3, b3, out);
}